// round 1
// baseline (speedup 1.0000x reference)
#include <cuda_runtime.h>
#include <math_constants.h>

#define B_CONST 4096
#define D_CONST 256
#define N_CONST 8192

// scratch (device globals — no allocation allowed)
__device__ float g_maxfeat[N_CONST];
__device__ int   g_idxmax[N_CONST];

__global__ void zero_out_kernel(float* __restrict__ out, int n) {
    int i = blockIdx.x * blockDim.x + threadIdx.x;
    if (i < n) out[i] = 0.0f;
}

// One warp per row: max + argmax over D=256, histogram of argmax into hist[256].
__global__ void rowstats_kernel(const float* __restrict__ a,
                                const float* __restrict__ b,
                                float* __restrict__ hist) {
    int warp = (blockIdx.x * blockDim.x + threadIdx.x) >> 5;
    int lane = threadIdx.x & 31;
    if (warp >= N_CONST) return;

    const float* row = (warp < B_CONST)
        ? (a + (size_t)warp * D_CONST)
        : (b + (size_t)(warp - B_CONST) * D_CONST);

    float best = -CUDART_INF_F;
    int bidx = 0;
    // lane covers cols {4*lane..4*lane+3} and {+128}; increasing order per lane
    #pragma unroll
    for (int k = 0; k < D_CONST; k += 128) {
        int c = k + lane * 4;
        float4 v = *reinterpret_cast<const float4*>(row + c);
        if (v.x > best) { best = v.x; bidx = c;     }
        if (v.y > best) { best = v.y; bidx = c + 1; }
        if (v.z > best) { best = v.z; bidx = c + 2; }
        if (v.w > best) { best = v.w; bidx = c + 3; }
    }
    // warp reduce: max value, first-occurrence (min index) tie-break
    #pragma unroll
    for (int off = 16; off; off >>= 1) {
        float ov = __shfl_down_sync(0xffffffffu, best, off);
        int   oi = __shfl_down_sync(0xffffffffu, bidx, off);
        if (ov > best || (ov == best && oi < bidx)) { best = ov; bidx = oi; }
    }
    if (lane == 0) {
        g_maxfeat[warp] = best;
        g_idxmax[warp]  = bidx;
        atomicAdd(&hist[bidx], 1.0f);
    }
}

// One thread per row: gather two elements, accumulate loss.
__global__ void loss_kernel(const float* __restrict__ a,
                            const float* __restrict__ b,
                            const int* __restrict__ negc,
                            float* __restrict__ out_loss) {
    int i = blockIdx.x * blockDim.x + threadIdx.x;
    float contrib = 0.0f;
    if (i < N_CONST) {
        int pair = (i + B_CONST) & (N_CONST - 1);
        int e1 = min(i, pair);
        int e2 = max(i, pair);
        int c = negc[i];
        c += (c >= e1) ? 1 : 0;
        c += (c >= e2) ? 1 : 0;

        int j1 = g_idxmax[pair];
        int j2 = g_idxmax[c];

        const float* row = (i < B_CONST)
            ? (a + (size_t)i * D_CONST)
            : (b + (size_t)(i - B_CONST) * D_CONST);

        float mf  = g_maxfeat[i];
        float pos = mf - row[j1];           // positives[i]
        float neg = mf - row[j2];           // negatives[i]
        float m   = fmaxf(1.0f - neg, 0.0f); // clamp(MARGIN - neg, 0)
        contrib = pos + m * m;
    }

    // block reduce (256 threads = 8 warps)
    __shared__ float sm[8];
    #pragma unroll
    for (int off = 16; off; off >>= 1)
        contrib += __shfl_down_sync(0xffffffffu, contrib, off);
    if ((threadIdx.x & 31) == 0) sm[threadIdx.x >> 5] = contrib;
    __syncthreads();
    if (threadIdx.x == 0) {
        float v = 0.0f;
        #pragma unroll
        for (int w = 0; w < 8; w++) v += sm[w];
        atomicAdd(out_loss, 0.5f * v);  // sum(...)/2
    }
}

extern "C" void kernel_launch(void* const* d_in, const int* in_sizes, int n_in,
                              void* d_out, int out_size) {
    const float* a    = (const float*)d_in[0];   // out_a [4096,256] f32
    const float* b    = (const float*)d_in[1];   // out_b [4096,256] f32
    const int*   negc = (const int*)  d_in[2];   // neg_choice [8192] i32
    float* out = (float*)d_out;                  // [0]=loss, [1..256]=num_max

    // zero output (poisoned to 0xAA by harness)
    zero_out_kernel<<<(out_size + 255) / 256, 256>>>(out, out_size);

    // per-row max/argmax + histogram (num_max) into out+1
    rowstats_kernel<<<N_CONST / 8, 256>>>(a, b, out + 1);

    // loss reduction into out[0]
    loss_kernel<<<N_CONST / 256, 256>>>(a, b, negc, out);
}